// round 14
// baseline (speedup 1.0000x reference)
#include <cuda_runtime.h>
#include <cuda_bf16.h>
#include <stdint.h>

// ============================================================================
// SoftMesh MLP: [N,3] -> 50 -> 7x(50->50 tanh) -> 3
// R12 = R10 (warp mma.sync bf16 hi/lo split, 2 CTAs/SM) +
//  - division-free tanh: EX2 + bit-hack reciprocal + 3 Newton steps.
//    MUFU per tanh 2 -> 1 (MUFU was ~52% busy, co-bottleneck with tensor);
//    the Newton math lands on the under-used FMA pipe (22%).
//  - ITERS 8 -> 4: grid 1303 -> 2605 over 296 CTA slots = 8.80 -> 97.8%
//    last-wave efficiency (was 4.40 -> 88%, ~100us tail idle).
// ============================================================================

#define NHID  50
#define NMID  7
#define TPB   384
#define WARPS (TPB / 32)     // 12
#define ITERS 4
#define SPC   (WARPS * 16 * ITERS)   // samples per CTA = 768

typedef uint32_t u32;

// SMEM byte offsets
#define SM_FRAG  0                         // [7][7nt][4kt][32 lanes] x 16B
#define FRAG_L   (7 * 4 * 32)              // ulonglong2 entries per layer = 896
#define SM_BIAS  (7 * FRAG_L * 16)         // 100352: [7][64] f32
#define SM_WIN   (SM_BIAS + 7 * 64 * 4)    // 102144: [3][64] f32
#define SM_BIN   (SM_WIN + 3 * 64 * 4)     // 102912: [64] f32
#define SM_WOUT  (SM_BIN + 64 * 4)         // 103168: [64][4] f32
#define SM_BOUT  (SM_WOUT + 64 * 4 * 4)    // 104192: [4] f32
#define SMEM_BYTES (SM_BOUT + 16)          // 104208  (x2 CTAs = 208KB < 228KB)

// tanh(x) = 1 - 2/(e^{2x}+1); e^{2x} = 2^{x*2*log2(e)} via 1 MUFU.EX2.
// Reciprocal of d (in (1, ~2e4], no inf/nan possible: |pre-act| bounded by
// bias + sum|W| << 40) via bit-hack seed + 3 Newton steps (FMA pipe).
__device__ __forceinline__ float fast_tanh(float x) {
    float t;
    float u = x * 2.885390081777927f;       // 2*log2(e)
    asm("ex2.approx.f32 %0, %1;" : "=f"(t) : "f"(u));
    float d = t + 1.0f;
    float y = __uint_as_float(0x7EF311C3u - __float_as_uint(d));
    y = y * fmaf(-d, y, 2.0f);
    y = y * fmaf(-d, y, 2.0f);
    y = y * fmaf(-d, y, 2.0f);
    return fmaf(-2.0f, y, 1.0f);
}

// pack two f32 -> bf16x2: low half = f0, high half = f1
__device__ __forceinline__ u32 bf2(float f0, float f1) {
    u32 r;
    asm("cvt.rn.bf16x2.f32 %0, %1, %2;" : "=r"(r) : "f"(f1), "f"(f0));
    return r;
}

// hi = bf16 round of (f0,f1); lo = residual pair, also bf16
__device__ __forceinline__ void make_ahl(float f0, float f1, u32& hi, u32& lo) {
    u32 hw = bf2(f0, f1);
    float h0 = __uint_as_float(hw << 16);
    float h1 = __uint_as_float(hw & 0xffff0000u);
    hi = hw;
    lo = bf2(f0 - h0, f1 - h1);
}

__device__ __forceinline__ void mma16816(float* c, const u32* a, u32 b0, u32 b1) {
    asm volatile(
        "mma.sync.aligned.m16n8k16.row.col.f32.bf16.bf16.f32 "
        "{%0,%1,%2,%3}, {%4,%5,%6,%7}, {%8,%9}, {%0,%1,%2,%3};"
        : "+f"(c[0]), "+f"(c[1]), "+f"(c[2]), "+f"(c[3])
        : "r"(a[0]), "r"(a[1]), "r"(a[2]), "r"(a[3]), "r"(b0), "r"(b1));
}

extern __shared__ char smem[];

__global__ void __launch_bounds__(TPB, 2)
softmesh_mma_kernel(const float* __restrict__ x,
                    const float* __restrict__ y,
                    const float* __restrict__ z,
                    const float* __restrict__ W_in,   // [3,50]
                    const float* __restrict__ b_in,   // [50]
                    const float* __restrict__ W_mid,  // [7,50,50]
                    const float* __restrict__ b_mid,  // [7,50]
                    const float* __restrict__ W_out,  // [50,3]
                    const float* __restrict__ b_out,  // [3]
                    float* __restrict__ out,          // [3N]
                    int n) {
    const int tid = threadIdx.x;

    // ---------------- Build weight fragments in SMEM ----------------
    // B-fragment (m16n8k16, col-major KxN): lane q=lane&3, nl=lane>>2.
    //   b0 = {W[k0][n], W[k0+1][n]},  b1 = {W[k0+8][n], W[k0+9][n]},
    //   k0 = 16*kt + 2*q, n = 8*nt + nl.
    // Entry = ulonglong2 { x = {b0h, b1h}, y = {b0l, b1l} }.
    {
        ulonglong2* frag = (ulonglong2*)(smem + SM_FRAG);
        for (int i = tid; i < NMID * FRAG_L; i += TPB) {
            int lane = i & 31;
            int kt = (i >> 5) & 3;
            int nt = (i >> 7) % 7;
            int l  = i / FRAG_L;
            int q = lane & 3, nl = lane >> 2;
            int nn = nt * 8 + nl;
            int k0 = kt * 16 + q * 2;
            float w[4];
#pragma unroll
            for (int j = 0; j < 4; j++) {
                int k = k0 + (j >> 1) * 8 + (j & 1);
                w[j] = (k < NHID && nn < NHID)
                     ? W_mid[(l * NHID + k) * NHID + nn] : 0.0f;
            }
            u32 b0h, b0l, b1h, b1l;
            make_ahl(w[0], w[1], b0h, b0l);
            make_ahl(w[2], w[3], b1h, b1l);
            ulonglong2 e;
            e.x = ((unsigned long long)b1h << 32) | b0h;
            e.y = ((unsigned long long)b1l << 32) | b0l;
            frag[i] = e;
        }
        float* bias = (float*)(smem + SM_BIAS);
        for (int i = tid; i < NMID * 64; i += TPB) {
            int l = i >> 6, c = i & 63;
            bias[i] = (c < NHID) ? b_mid[l * NHID + c] : 0.0f;
        }
        float* win = (float*)(smem + SM_WIN);
        for (int i = tid; i < 3 * 64; i += TPB) {
            int r = i >> 6, c = i & 63;
            win[i] = (c < NHID) ? W_in[r * NHID + c] : 0.0f;
        }
        float* bin = (float*)(smem + SM_BIN);
        for (int i = tid; i < 64; i += TPB)
            bin[i] = (i < NHID) ? b_in[i] : 0.0f;
        float* wout = (float*)(smem + SM_WOUT);
        for (int i = tid; i < 64 * 4; i += TPB) {
            int c = i >> 2, j = i & 3;
            wout[i] = (c < NHID && j < 3) ? W_out[c * 3 + j] : 0.0f;
        }
        if (tid < 3) ((float*)(smem + SM_BOUT))[tid] = b_out[tid];
    }
    __syncthreads();

    const int warp = tid >> 5;
    const int lane = tid & 31;
    const int q = lane & 3;
    const int r = lane >> 2;          // row 0..7 within m16 tile

    const float* win  = (const float*)(smem + SM_WIN);
    const float* bin  = (const float*)(smem + SM_BIN);
    const float* bias = (const float*)(smem + SM_BIAS);
    const float* wout = (const float*)(smem + SM_WOUT);
    const ulonglong2* frag = (const ulonglong2*)(smem + SM_FRAG);

#pragma unroll 1
    for (int it = 0; it < ITERS; it++) {
        const int base = blockIdx.x * SPC + it * (WARPS * 16) + warp * 16;
        const int s0 = base + r;          // row r
        const int s1 = base + r + 8;      // row r+8
        const int s0c = (s0 < n) ? s0 : (n - 1);
        const int s1c = (s1 < n) ? s1 : (n - 1);

        const float x0 = x[s0c], y0 = y[s0c], z0 = z[s0c];
        const float x1 = x[s1c], y1 = y[s1c], z1 = z[s1c];

        u32 ah[4][4], al[4][4];

        // ---------------- Input layer (scalar) -> A fragments ----------------
        // h(row, c) = tanh(b_in[c] + x*Win0[c] + y*Win1[c] + z*Win2[c]), c<50.
#pragma unroll
        for (int kt = 0; kt < 4; kt++) {
#pragma unroll
            for (int half = 0; half < 2; half++) {        // half=0: k0.. ; 1: k0+8
                int c0 = kt * 16 + q * 2 + half * 8;
                float t00 = 0.0f, t01 = 0.0f, t10 = 0.0f, t11 = 0.0f;
                if (c0 < NHID) {
                    float p0 = fmaf(x0, win[c0], bin[c0]);
                    p0 = fmaf(y0, win[64 + c0], p0);
                    p0 = fmaf(z0, win[128 + c0], p0);
                    t00 = fast_tanh(p0);
                    float p1 = fmaf(x1, win[c0], bin[c0]);
                    p1 = fmaf(y1, win[64 + c0], p1);
                    p1 = fmaf(z1, win[128 + c0], p1);
                    t10 = fast_tanh(p1);
                }
                if (c0 + 1 < NHID) {
                    int c1 = c0 + 1;
                    float p0 = fmaf(x0, win[c1], bin[c1]);
                    p0 = fmaf(y0, win[64 + c1], p0);
                    p0 = fmaf(z0, win[128 + c1], p0);
                    t01 = fast_tanh(p0);
                    float p1 = fmaf(x1, win[c1], bin[c1]);
                    p1 = fmaf(y1, win[64 + c1], p1);
                    p1 = fmaf(z1, win[128 + c1], p1);
                    t11 = fast_tanh(p1);
                }
                make_ahl(t00, t01, ah[kt][0 + 2 * half], al[kt][0 + 2 * half]);
                make_ahl(t10, t11, ah[kt][1 + 2 * half], al[kt][1 + 2 * half]);
            }
        }

        float t[7][4];

        // ---------------- 7 mid layers via HMMA ----------------
#pragma unroll 1
        for (int l = 0; l < NMID; l++) {
            float c[7][4];
#pragma unroll
            for (int nt = 0; nt < 7; nt++) {
                int col0 = nt * 8 + q * 2;
                float bv0 = bias[l * 64 + col0];
                float bv1 = bias[l * 64 + col0 + 1];
                c[nt][0] = bv0; c[nt][1] = bv1;
                c[nt][2] = bv0; c[nt][3] = bv1;
            }
            const ulonglong2* fl = frag + l * FRAG_L;
#pragma unroll
            for (int nt = 0; nt < 7; nt++) {
#pragma unroll
                for (int kt = 0; kt < 4; kt++) {
                    ulonglong2 B = fl[(nt * 4 + kt) * 32 + lane];  // LDS.128
                    u32 b0h = (u32)B.x, b1h = (u32)(B.x >> 32);
                    u32 b0l = (u32)B.y, b1l = (u32)(B.y >> 32);
                    mma16816(c[nt], ah[kt], b0h, b1h);
                    mma16816(c[nt], ah[kt], b0l, b1l);
                    mma16816(c[nt], al[kt], b0h, b1h);
                }
            }
            // epilogue: tanh + repack accumulators as next layer's A fragments
#pragma unroll
            for (int nt = 0; nt < 7; nt++) {
#pragma unroll
                for (int j = 0; j < 4; j++) t[nt][j] = fast_tanh(c[nt][j]);
            }
            if (l == NMID - 1) break;
#pragma unroll
            for (int kt = 0; kt < 4; kt++) {
                int nt0 = 2 * kt;
                make_ahl(t[nt0][0], t[nt0][1], ah[kt][0], al[kt][0]);
                make_ahl(t[nt0][2], t[nt0][3], ah[kt][1], al[kt][1]);
                if (kt < 3) {
                    int nt1 = nt0 + 1;
                    make_ahl(t[nt1][0], t[nt1][1], ah[kt][2], al[kt][2]);
                    make_ahl(t[nt1][2], t[nt1][3], ah[kt][3], al[kt][3]);
                } else {
                    ah[kt][2] = ah[kt][3] = 0u;   // cols 56..63: weights are 0
                    al[kt][2] = al[kt][3] = 0u;
                }
            }
        }

        // ---------------- Output layer: U = h @ W_out + b_out ----------------
        float u00 = 0.0f, u01 = 0.0f, u02 = 0.0f;   // row r
        float u10 = 0.0f, u11 = 0.0f, u12 = 0.0f;   // row r+8
#pragma unroll
        for (int nt = 0; nt < 7; nt++) {
            int col0 = nt * 8 + q * 2;
            const float4 w0 = *(const float4*)(wout + col0 * 4);       // col0 (0 if >=50)
            const float4 w1 = *(const float4*)(wout + (col0 + 1) * 4); // col0+1
            u00 = fmaf(t[nt][0], w0.x, u00); u00 = fmaf(t[nt][1], w1.x, u00);
            u01 = fmaf(t[nt][0], w0.y, u01); u01 = fmaf(t[nt][1], w1.y, u01);
            u02 = fmaf(t[nt][0], w0.z, u02); u02 = fmaf(t[nt][1], w1.z, u02);
            u10 = fmaf(t[nt][2], w0.x, u10); u10 = fmaf(t[nt][3], w1.x, u10);
            u11 = fmaf(t[nt][2], w0.y, u11); u11 = fmaf(t[nt][3], w1.y, u11);
            u12 = fmaf(t[nt][2], w0.z, u12); u12 = fmaf(t[nt][3], w1.z, u12);
        }
        // reduce across the 4 q-lanes of each row
#pragma unroll
        for (int off = 1; off <= 2; off <<= 1) {
            u00 += __shfl_xor_sync(0xffffffffu, u00, off);
            u01 += __shfl_xor_sync(0xffffffffu, u01, off);
            u02 += __shfl_xor_sync(0xffffffffu, u02, off);
            u10 += __shfl_xor_sync(0xffffffffu, u10, off);
            u11 += __shfl_xor_sync(0xffffffffu, u11, off);
            u12 += __shfl_xor_sync(0xffffffffu, u12, off);
        }
        if (q == 0) {
            const float b0v = ((const float*)(smem + SM_BOUT))[0];
            const float b1v = ((const float*)(smem + SM_BOUT))[1];
            const float b2v = ((const float*)(smem + SM_BOUT))[2];
            if (s0 < n) {
                out[s0]         = u00 + b0v;
                out[n + s0]     = u01 + b1v;
                out[2 * n + s0] = u02 + b2v;
            }
            if (s1 < n) {
                out[s1]         = u10 + b0v;
                out[n + s1]     = u11 + b1v;
                out[2 * n + s1] = u12 + b2v;
            }
        }
    }
}

extern "C" void kernel_launch(void* const* d_in, const int* in_sizes, int n_in,
                              void* d_out, int out_size) {
    const float* x     = (const float*)d_in[0];
    const float* y     = (const float*)d_in[1];
    const float* z     = (const float*)d_in[2];
    const float* W_in  = (const float*)d_in[3];
    const float* b_in  = (const float*)d_in[4];
    const float* W_mid = (const float*)d_in[5];
    const float* b_mid = (const float*)d_in[6];
    const float* W_out = (const float*)d_in[7];
    const float* b_out = (const float*)d_in[8];
    float* out = (float*)d_out;

    const int n = in_sizes[0];

    cudaFuncSetAttribute(softmesh_mma_kernel,
                         cudaFuncAttributeMaxDynamicSharedMemorySize, SMEM_BYTES);

    const int blocks = (n + SPC - 1) / SPC;
    softmesh_mma_kernel<<<blocks, TPB, SMEM_BYTES>>>(
        x, y, z, W_in, b_in, W_mid, b_mid, W_out, b_out, out, n);
}

// round 16
// speedup vs baseline: 1.1616x; 1.1616x over previous
#include <cuda_runtime.h>
#include <cuda_bf16.h>
#include <stdint.h>

// ============================================================================
// SoftMesh MLP: [N,3] -> 50 -> 7x(50->50 tanh) -> 3
// R14 = R10 (best tensor kernel: warp mma.sync bf16 hi/lo split, 2 CTAs/SM)
//   + ITERS 8 -> 4 (wave quantization 88% -> 97.8%)   [kept from R12]
//   + tanh reverted to __expf/__fdividef (R12's Newton tanh ADDED issue
//     slots; kernel is issue-bound -> fewest instructions wins)
//   + kt-outer / nt-inner MMA order: consecutive HMMAs hit different
//     accumulators (7 independent chains vs 12 serial per accumulator)
//   + guard-free input layer (zero-padded weights), float2 bias loads
// ============================================================================

#define NHID  50
#define NMID  7
#define TPB   384
#define WARPS (TPB / 32)     // 12
#define ITERS 4
#define SPC   (WARPS * 16 * ITERS)   // samples per CTA = 768

typedef uint32_t u32;

// SMEM byte offsets
#define SM_FRAG  0                         // [7][7nt][4kt][32 lanes] x 16B
#define FRAG_L   (7 * 4 * 32)              // ulonglong2 entries per layer = 896
#define SM_BIAS  (7 * FRAG_L * 16)         // 100352: [7][64] f32
#define SM_WIN   (SM_BIAS + 7 * 64 * 4)    // 102144: [3][64] f32
#define SM_BIN   (SM_WIN + 3 * 64 * 4)     // 102912: [64] f32
#define SM_WOUT  (SM_BIN + 64 * 4)         // 103168: [64][4] f32
#define SM_BOUT  (SM_WOUT + 64 * 4 * 4)    // 104192: [4] f32
#define SMEM_BYTES (SM_BOUT + 16)          // 104208  (x2 CTAs = 208KB < 228KB)

// Cheapest-in-issue-slots tanh: 1 mul + MUFU.EX2 + add + MUFU.RCP + mul + add.
__device__ __forceinline__ float fast_tanh(float x) {
    float e = __expf(2.0f * x);
    return 1.0f - __fdividef(2.0f, e + 1.0f);
}

// pack two f32 -> bf16x2: low half = f0, high half = f1
__device__ __forceinline__ u32 bf2(float f0, float f1) {
    u32 r;
    asm("cvt.rn.bf16x2.f32 %0, %1, %2;" : "=r"(r) : "f"(f1), "f"(f0));
    return r;
}

// hi = bf16 round of (f0,f1); lo = residual pair, also bf16
__device__ __forceinline__ void make_ahl(float f0, float f1, u32& hi, u32& lo) {
    u32 hw = bf2(f0, f1);
    float h0 = __uint_as_float(hw << 16);
    float h1 = __uint_as_float(hw & 0xffff0000u);
    hi = hw;
    lo = bf2(f0 - h0, f1 - h1);
}

__device__ __forceinline__ void mma16816(float* c, const u32* a, u32 b0, u32 b1) {
    asm volatile(
        "mma.sync.aligned.m16n8k16.row.col.f32.bf16.bf16.f32 "
        "{%0,%1,%2,%3}, {%4,%5,%6,%7}, {%8,%9}, {%0,%1,%2,%3};"
        : "+f"(c[0]), "+f"(c[1]), "+f"(c[2]), "+f"(c[3])
        : "r"(a[0]), "r"(a[1]), "r"(a[2]), "r"(a[3]), "r"(b0), "r"(b1));
}

extern __shared__ char smem[];

__global__ void __launch_bounds__(TPB, 2)
softmesh_mma_kernel(const float* __restrict__ x,
                    const float* __restrict__ y,
                    const float* __restrict__ z,
                    const float* __restrict__ W_in,   // [3,50]
                    const float* __restrict__ b_in,   // [50]
                    const float* __restrict__ W_mid,  // [7,50,50]
                    const float* __restrict__ b_mid,  // [7,50]
                    const float* __restrict__ W_out,  // [50,3]
                    const float* __restrict__ b_out,  // [3]
                    float* __restrict__ out,          // [3N]
                    int n) {
    const int tid = threadIdx.x;

    // ---------------- Build weight fragments in SMEM ----------------
    // B-fragment (m16n8k16, col-major KxN): lane q=lane&3, nl=lane>>2.
    //   b0 = {W[k0][n], W[k0+1][n]},  b1 = {W[k0+8][n], W[k0+9][n]},
    //   k0 = 16*kt + 2*q, n = 8*nt + nl.
    // Entry = ulonglong2 { x = {b0h, b1h}, y = {b0l, b1l} }.
    {
        ulonglong2* frag = (ulonglong2*)(smem + SM_FRAG);
        for (int i = tid; i < NMID * FRAG_L; i += TPB) {
            int lane = i & 31;
            int kt = (i >> 5) & 3;
            int nt = (i >> 7) % 7;
            int l  = i / FRAG_L;
            int q = lane & 3, nl = lane >> 2;
            int nn = nt * 8 + nl;
            int k0 = kt * 16 + q * 2;
            float w[4];
#pragma unroll
            for (int j = 0; j < 4; j++) {
                int k = k0 + (j >> 1) * 8 + (j & 1);
                w[j] = (k < NHID && nn < NHID)
                     ? W_mid[(l * NHID + k) * NHID + nn] : 0.0f;
            }
            u32 b0h, b0l, b1h, b1l;
            make_ahl(w[0], w[1], b0h, b0l);
            make_ahl(w[2], w[3], b1h, b1l);
            ulonglong2 e;
            e.x = ((unsigned long long)b1h << 32) | b0h;
            e.y = ((unsigned long long)b1l << 32) | b0l;
            frag[i] = e;
        }
        float* bias = (float*)(smem + SM_BIAS);
        for (int i = tid; i < NMID * 64; i += TPB) {
            int l = i >> 6, c = i & 63;
            bias[i] = (c < NHID) ? b_mid[l * NHID + c] : 0.0f;
        }
        float* win = (float*)(smem + SM_WIN);
        for (int i = tid; i < 3 * 64; i += TPB) {
            int r = i >> 6, c = i & 63;
            win[i] = (c < NHID) ? W_in[r * NHID + c] : 0.0f;
        }
        float* bin = (float*)(smem + SM_BIN);
        for (int i = tid; i < 64; i += TPB)
            bin[i] = (i < NHID) ? b_in[i] : 0.0f;
        float* wout = (float*)(smem + SM_WOUT);
        for (int i = tid; i < 64 * 4; i += TPB) {
            int c = i >> 2, j = i & 3;
            wout[i] = (c < NHID && j < 3) ? W_out[c * 3 + j] : 0.0f;
        }
        if (tid < 3) ((float*)(smem + SM_BOUT))[tid] = b_out[tid];
    }
    __syncthreads();

    const int warp = tid >> 5;
    const int lane = tid & 31;
    const int q = lane & 3;
    const int r = lane >> 2;          // row 0..7 within m16 tile

    const float* win  = (const float*)(smem + SM_WIN);
    const float* bin  = (const float*)(smem + SM_BIN);
    const float* bias = (const float*)(smem + SM_BIAS);
    const float* wout = (const float*)(smem + SM_WOUT);
    const ulonglong2* frag = (const ulonglong2*)(smem + SM_FRAG);

#pragma unroll 1
    for (int it = 0; it < ITERS; it++) {
        const int base = blockIdx.x * SPC + it * (WARPS * 16) + warp * 16;
        const int s0 = base + r;          // row r
        const int s1 = base + r + 8;      // row r+8
        const int s0c = (s0 < n) ? s0 : (n - 1);
        const int s1c = (s1 < n) ? s1 : (n - 1);

        const float x0 = x[s0c], y0 = y[s0c], z0 = z[s0c];
        const float x1 = x[s1c], y1 = y[s1c], z1 = z[s1c];

        u32 ah[4][4], al[4][4];

        // ---------------- Input layer (scalar) -> A fragments ----------------
        // h(row, c) = tanh(b_in[c] + x*W0[c] + y*W1[c] + z*W2[c]).
        // win/bin zero-padded to 64 cols -> no bounds guards needed (tanh(0)=0).
#pragma unroll
        for (int kt = 0; kt < 4; kt++) {
#pragma unroll
            for (int half = 0; half < 2; half++) {        // half=0: k0.. ; 1: k0+8
                int c0 = kt * 16 + q * 2 + half * 8;
                int c1 = c0 + 1;
                float p;
                p = fmaf(x0, win[c0], bin[c0]);
                p = fmaf(y0, win[64 + c0], p);
                p = fmaf(z0, win[128 + c0], p);
                float t00 = fast_tanh(p);
                float t01;
                p = fmaf(x0, win[c1], bin[c1]);
                p = fmaf(y0, win[64 + c1], p);
                p = fmaf(z0, win[128 + c1], p);
                t01 = fast_tanh(p);
                p = fmaf(x1, win[c0], bin[c0]);
                p = fmaf(y1, win[64 + c0], p);
                p = fmaf(z1, win[128 + c0], p);
                float t10 = fast_tanh(p);
                float t11;
                p = fmaf(x1, win[c1], bin[c1]);
                p = fmaf(y1, win[64 + c1], p);
                p = fmaf(z1, win[128 + c1], p);
                t11 = fast_tanh(p);
                make_ahl(t00, t01, ah[kt][0 + 2 * half], al[kt][0 + 2 * half]);
                make_ahl(t10, t11, ah[kt][1 + 2 * half], al[kt][1 + 2 * half]);
            }
        }

        float t[7][4];

        // ---------------- 7 mid layers via HMMA ----------------
#pragma unroll 1
        for (int l = 0; l < NMID; l++) {
            float c[7][4];
#pragma unroll
            for (int nt = 0; nt < 7; nt++) {
                const float2 bv = *(const float2*)(bias + l * 64 + nt * 8 + q * 2);
                c[nt][0] = bv.x; c[nt][1] = bv.y;
                c[nt][2] = bv.x; c[nt][3] = bv.y;
            }
            const ulonglong2* fl = frag + l * FRAG_L;
            // kt outer / nt inner: consecutive MMAs hit different accumulators
            // (7 independent dependency chains for the tensor pipe).
#pragma unroll
            for (int kt = 0; kt < 4; kt++) {
#pragma unroll
                for (int nt = 0; nt < 7; nt++) {
                    ulonglong2 B = fl[(nt * 4 + kt) * 32 + lane];  // LDS.128
                    u32 b0h = (u32)B.x, b1h = (u32)(B.x >> 32);
                    u32 b0l = (u32)B.y, b1l = (u32)(B.y >> 32);
                    mma16816(c[nt], ah[kt], b0h, b1h);
                    mma16816(c[nt], ah[kt], b0l, b1l);
                    mma16816(c[nt], al[kt], b0h, b1h);
                }
            }
            // epilogue: tanh + repack accumulators as next layer's A fragments
#pragma unroll
            for (int nt = 0; nt < 7; nt++) {
#pragma unroll
                for (int j = 0; j < 4; j++) t[nt][j] = fast_tanh(c[nt][j]);
            }
            if (l == NMID - 1) break;
#pragma unroll
            for (int kt = 0; kt < 4; kt++) {
                int nt0 = 2 * kt;
                make_ahl(t[nt0][0], t[nt0][1], ah[kt][0], al[kt][0]);
                make_ahl(t[nt0][2], t[nt0][3], ah[kt][1], al[kt][1]);
                if (kt < 3) {
                    int nt1 = nt0 + 1;
                    make_ahl(t[nt1][0], t[nt1][1], ah[kt][2], al[kt][2]);
                    make_ahl(t[nt1][2], t[nt1][3], ah[kt][3], al[kt][3]);
                } else {
                    ah[kt][2] = ah[kt][3] = 0u;   // cols 56..63: weights are 0
                    al[kt][2] = al[kt][3] = 0u;
                }
            }
        }

        // ---------------- Output layer: U = h @ W_out + b_out ----------------
        float u00 = 0.0f, u01 = 0.0f, u02 = 0.0f;   // row r
        float u10 = 0.0f, u11 = 0.0f, u12 = 0.0f;   // row r+8
#pragma unroll
        for (int nt = 0; nt < 7; nt++) {
            int col0 = nt * 8 + q * 2;
            const float4 w0 = *(const float4*)(wout + col0 * 4);       // col0 (0 if >=50)
            const float4 w1 = *(const float4*)(wout + (col0 + 1) * 4); // col0+1
            u00 = fmaf(t[nt][0], w0.x, u00); u00 = fmaf(t[nt][1], w1.x, u00);
            u01 = fmaf(t[nt][0], w0.y, u01); u01 = fmaf(t[nt][1], w1.y, u01);
            u02 = fmaf(t[nt][0], w0.z, u02); u02 = fmaf(t[nt][1], w1.z, u02);
            u10 = fmaf(t[nt][2], w0.x, u10); u10 = fmaf(t[nt][3], w1.x, u10);
            u11 = fmaf(t[nt][2], w0.y, u11); u11 = fmaf(t[nt][3], w1.y, u11);
            u12 = fmaf(t[nt][2], w0.z, u12); u12 = fmaf(t[nt][3], w1.z, u12);
        }
        // reduce across the 4 q-lanes of each row
#pragma unroll
        for (int off = 1; off <= 2; off <<= 1) {
            u00 += __shfl_xor_sync(0xffffffffu, u00, off);
            u01 += __shfl_xor_sync(0xffffffffu, u01, off);
            u02 += __shfl_xor_sync(0xffffffffu, u02, off);
            u10 += __shfl_xor_sync(0xffffffffu, u10, off);
            u11 += __shfl_xor_sync(0xffffffffu, u11, off);
            u12 += __shfl_xor_sync(0xffffffffu, u12, off);
        }
        if (q == 0) {
            const float b0v = ((const float*)(smem + SM_BOUT))[0];
            const float b1v = ((const float*)(smem + SM_BOUT))[1];
            const float b2v = ((const float*)(smem + SM_BOUT))[2];
            if (s0 < n) {
                out[s0]         = u00 + b0v;
                out[n + s0]     = u01 + b1v;
                out[2 * n + s0] = u02 + b2v;
            }
            if (s1 < n) {
                out[s1]         = u10 + b0v;
                out[n + s1]     = u11 + b1v;
                out[2 * n + s1] = u12 + b2v;
            }
        }
    }
}

extern "C" void kernel_launch(void* const* d_in, const int* in_sizes, int n_in,
                              void* d_out, int out_size) {
    const float* x     = (const float*)d_in[0];
    const float* y     = (const float*)d_in[1];
    const float* z     = (const float*)d_in[2];
    const float* W_in  = (const float*)d_in[3];
    const float* b_in  = (const float*)d_in[4];
    const float* W_mid = (const float*)d_in[5];
    const float* b_mid = (const float*)d_in[6];
    const float* W_out = (const float*)d_in[7];
    const float* b_out = (const float*)d_in[8];
    float* out = (float*)d_out;

    const int n = in_sizes[0];

    cudaFuncSetAttribute(softmesh_mma_kernel,
                         cudaFuncAttributeMaxDynamicSharedMemorySize, SMEM_BYTES);

    const int blocks = (n + SPC - 1) / SPC;
    softmesh_mma_kernel<<<blocks, TPB, SMEM_BYTES>>>(
        x, y, z, W_in, b_in, W_mid, b_mid, W_out, b_out, out, n);
}